// round 17
// baseline (speedup 1.0000x reference)
#include <cuda_runtime.h>
#include <cuda_fp16.h>
#include <stdint.h>
#include <math.h>

#define H 128
#define W 128
#define HW (H*W)
#define NF 64
#define TT 5
#define BB 2

// ---------------- scratch ----------------
__device__ __half g_fnhwc_h[BB*TT*HW*NF];    // NHWC fp16 features
__device__ float g_half[BB*6*27*HW];         // half offset-conv outputs (fp32)
__device__ __half g_wth[9*64*64];            // dcn weights fp16, [k][o][swizzled-c]
__device__ __half g_hwh[2*9*32*64];          // half-conv weights fp16, [icg][tap][oc32][c-swizzled]

// ---------------- helpers ----------------
typedef unsigned long long ull;
__device__ __forceinline__ ull pk2(float lo, float hi) {
    ull r; asm("mov.b64 %0, {%1,%2};" : "=l"(r) : "f"(lo), "f"(hi)); return r;
}
__device__ __forceinline__ void ffma2(ull& d, ull a, ull b) {
    asm("fma.rn.f32x2 %0, %1, %2, %0;" : "+l"(d) : "l"(a), "l"(b));
}
__device__ __forceinline__ float2 upk2(ull v) {
    float2 f; asm("mov.b64 {%0,%1}, %2;" : "=f"(f.x), "=f"(f.y) : "l"(v)); return f;
}
__device__ __forceinline__ void cp_async16(uint32_t saddr, const void* g, bool pred) {
    int bytes = pred ? 16 : 0;
    asm volatile("cp.async.ca.shared.global [%0], [%1], 16, %2;" :: "r"(saddr), "l"(g), "r"(bytes));
}
__device__ __forceinline__ void mma16816(float* d, const uint32_t* a, const uint32_t* b) {
    asm volatile(
        "mma.sync.aligned.m16n8k16.row.col.f32.f16.f16.f32 "
        "{%0,%1,%2,%3},{%4,%5,%6,%7},{%8,%9},{%0,%1,%2,%3};"
        : "+f"(d[0]), "+f"(d[1]), "+f"(d[2]), "+f"(d[3])
        : "r"(a[0]), "r"(a[1]), "r"(a[2]), "r"(a[3]), "r"(b[0]), "r"(b[1]));
}
__device__ __forceinline__ void ldsm_x4(uint32_t& r0, uint32_t& r1, uint32_t& r2, uint32_t& r3, uint32_t saddr) {
    asm volatile("ldmatrix.sync.aligned.m8n8.x4.shared.b16 {%0,%1,%2,%3}, [%4];"
                 : "=r"(r0), "=r"(r1), "=r"(r2), "=r"(r3) : "r"(saddr));
}

// ---------------- W-prep: dcn weights -> fp16 swizzled [k][o][c'] ----------------
__global__ void wth_prep_kernel(const float* __restrict__ dcn_w) {
    int i = blockIdx.x * blockDim.x + threadIdx.x;
    if (i >= 9*64*64) return;
    int k = i >> 12;
    int rest = i & 4095;
    int o = rest >> 6;
    int c = rest & 63;
    int u = c >> 3;
    int pos = (((u ^ (o & 7)) << 3) | (c & 7));
    g_wth[k*4096 + o*64 + pos] = __float2half(dcn_w[(o*64 + c)*9 + k]);
}

// ---------------- W-prep: half-conv weights fp16 [icg][tap][oc32][c-swizzled] ----------------
__global__ void hwh_prep_kernel(const float* __restrict__ offm_w) {
    int i = blockIdx.x * blockDim.x + threadIdx.x;
    if (i >= 2*9*32*64) return;
    int c = i & 63;
    int r = i >> 6;
    int oc = r & 31; r >>= 5;
    int tap = r % 9;
    int icg = r / 9;
    float v = 0.f;
    if (oc < 27) v = offm_w[(oc*128 + icg*64 + c)*9 + tap];
    int u = c >> 3;
    int pos = (((u ^ (oc & 7)) << 3) | (c & 7));
    g_hwh[(((size_t)icg*9 + tap)*32 + oc)*64 + pos] = __float2half(v);
}

// ---------------- kernel A: 3->64 conv3x3 + bias + PReLU -> NHWC fp16 directly ----------------
__global__ void __launch_bounds__(256) init_conv_kernel(
    const float* __restrict__ x, const float* __restrict__ wgt,
    const float* __restrict__ bias, const float* __restrict__ prelu_a)
{
    __shared__ float sx[3][18][18];
    __shared__ __align__(8) float sw[27*64];
    __shared__ __align__(8) float sb[64];
    int tid = threadIdx.x;
    int n = blockIdx.y;
    int ty0 = (blockIdx.x >> 3) * 16;
    int tx0 = (blockIdx.x & 7) * 16;

    for (int idx = tid; idx < 1728; idx += 256) {
        int oc = idx & 63;
        int r = idx >> 6;
        int ic = r / 9, tap = r % 9;
        sw[idx] = wgt[(oc*3 + ic)*9 + tap];
    }
    if (tid < 64) sb[tid] = bias[tid];

    const float* xin = x + n*3*HW;
    for (int idx = tid; idx < 3*18*18; idx += 256) {
        int c = idx / 324;
        int r = (idx / 18) % 18;
        int col = idx % 18;
        int gy = ty0 + r - 1, gx = tx0 + col - 1;
        float v = 0.f;
        if (gy >= 0 && gy < H && gx >= 0 && gx < W) v = xin[c*HW + gy*W + gx];
        sx[c][r][col] = v;
    }
    __syncthreads();

    int ly = tid >> 4, lx = tid & 15;
    ull acc2[32];
    #pragma unroll
    for (int o2 = 0; o2 < 32; o2++) acc2[o2] = *(const ull*)&sb[2*o2];

    for (int ic = 0; ic < 3; ic++) {
        #pragma unroll
        for (int tap = 0; tap < 9; tap++) {
            int dy = tap / 3, dx = tap % 3;
            float v = sx[ic][ly + dy][lx + dx];
            ull v2 = pk2(v, v);
            const ull* wp = (const ull*)&sw[(ic*9 + tap)*64];
            #pragma unroll
            for (int o2 = 0; o2 < 32; o2++) ffma2(acc2[o2], v2, wp[o2]);
        }
    }
    float a = prelu_a[0];
    int pix = (ty0 + ly)*W + (tx0 + lx);
    __half* nd = g_fnhwc_h + ((size_t)n*HW + pix)*64;
    #pragma unroll
    for (int g4 = 0; g4 < 8; g4++) {
        uint4 pkv;
        uint32_t* pp = (uint32_t*)&pkv;
        #pragma unroll
        for (int i = 0; i < 4; i++) {
            float2 f = upk2(acc2[g4*4 + i]);
            float h0v = (f.x > 0.f) ? f.x : a*f.x;
            float h1v = (f.y > 0.f) ? f.y : a*f.y;
            __half2 h = __float22half2_rn(make_float2(h0v, h1v));
            pp[i] = *(uint32_t*)&h;
        }
        *(uint4*)(nd + g4*8) = pkv;
    }
}

// ---------------- kernel B v9: half offset-conv via HMMA + ldmatrix (R16 verbatim) ----------------
__global__ void __launch_bounds__(128, 3) half_conv_kernel()
{
    extern __shared__ __align__(16) char Sb[];
    const int WOFF = 50688;
    int tid = threadIdx.x;
    int task = blockIdx.y;
    int b = task / 6, s = task % 6;
    int tsel = (s == 0) ? 0 : (s - 1);
    int icg  = (s == 0) ? 0 : 1;
    int y = blockIdx.x;

    const __half* fbh = g_fnhwc_h + (size_t)(b*TT + tsel)*HW*64;
    const char* wbase = (const char*)(g_hwh + (size_t)icg*9*32*64);
    uint32_t sbs = (uint32_t)__cvta_generic_to_shared(Sb);

    if (tid < 48) {
        int r = tid / 16;
        int side = (tid >> 3) & 1;
        int qq = tid & 7;
        int t = side ? 129 : 0;
        uint4 z = make_uint4(0, 0, 0, 0);
        *(uint4*)(Sb + (r*132 + t)*128 + ((qq ^ (t & 7)) << 4)) = z;
    }
    #pragma unroll
    for (int i = 0; i < 24; i++) {
        int idx = tid + i*128;
        int r = idx >> 10;
        int rem = idx & 1023;
        int t = 1 + (rem >> 3);
        int qq = rem & 7;
        int gy = y + r - 1;
        uint4 v = make_uint4(0, 0, 0, 0);
        if (gy >= 0 && gy < H) v = *(const uint4*)(fbh + ((size_t)gy*W + (t - 1))*64 + qq*8);
        *(uint4*)(Sb + (r*132 + t)*128 + ((qq ^ (t & 7)) << 4)) = v;
    }

    {
        #pragma unroll
        for (int i2 = 0; i2 < 2; i2++) {
            int idx = tid + i2*128;
            cp_async16(sbs + WOFF + idx*16, wbase + idx*16, true);
        }
        asm volatile("cp.async.commit_group;");
    }

    int lane = tid & 31;
    int warp = tid >> 5;
    int r4 = lane >> 2;
    int c2 = lane & 3;
    int w32 = warp * 32;

    int lrow  = lane & 7;
    int lhalf = (lane >> 3) & 1;
    int lkhi  = lane >> 4;
    int aRowOff = (lhalf*8 + lrow)*128;
    int bT0 = w32 + (lane >> 3)*8 + lrow;

    float acc[2][4][4];
    #pragma unroll
    for (int mt = 0; mt < 2; mt++)
        #pragma unroll
        for (int nt = 0; nt < 4; nt++)
            #pragma unroll
            for (int f = 0; f < 4; f++) acc[mt][nt][f] = 0.f;

    #pragma unroll
    for (int tap = 0; tap < 9; tap++) {
        int buf = tap & 1;
        if (tap < 8) {
            #pragma unroll
            for (int i2 = 0; i2 < 2; i2++) {
                int idx = tid + i2*128;
                cp_async16(sbs + WOFF + (buf^1)*4096 + idx*16, wbase + (tap+1)*4096 + idx*16, true);
            }
            asm volatile("cp.async.commit_group;");
            asm volatile("cp.async.wait_group 1;");
        } else {
            asm volatile("cp.async.wait_group 0;");
        }
        __syncthreads();

        int dy = tap / 3, dx = tap % 3;
        int t = bT0 + dx;
        uint32_t bRow = sbs + (dy*132 + t)*128;
        int tw = t & 7;
        uint32_t wBuf = sbs + WOFF + buf*4096;

        #pragma unroll
        for (int ks = 0; ks < 4; ks++) {
            uint32_t afr[2][4];
            #pragma unroll
            for (int mt = 0; mt < 2; mt++) {
                uint32_t sa = wBuf + mt*16*128 + aRowOff + ((uint32_t)((ks*2 + lkhi) ^ lrow) << 4);
                ldsm_x4(afr[mt][0], afr[mt][1], afr[mt][2], afr[mt][3], sa);
            }
            uint32_t blo[4], bhi[4];
            {
                uint32_t sb0 = bRow + ((uint32_t)((ks*2) ^ tw) << 4);
                ldsm_x4(blo[0], blo[1], blo[2], blo[3], sb0);
                uint32_t sb1 = bRow + ((uint32_t)((ks*2 + 1) ^ tw) << 4);
                ldsm_x4(bhi[0], bhi[1], bhi[2], bhi[3], sb1);
            }
            #pragma unroll
            for (int mt = 0; mt < 2; mt++)
                #pragma unroll
                for (int nt = 0; nt < 4; nt++) {
                    uint32_t bb[2] = { blo[nt], bhi[nt] };
                    mma16816(acc[mt][nt], afr[mt], bb);
                }
        }
        __syncthreads();
    }

    float* dst = g_half + (size_t)task*27*HW + y*W;
    #pragma unroll
    for (int mt = 0; mt < 2; mt++) {
        int oc0 = mt*16 + r4;
        int oc1 = oc0 + 8;
        #pragma unroll
        for (int nt = 0; nt < 4; nt++) {
            int px = w32 + nt*8 + c2*2;
            if (oc0 < 27) {
                float2 v; v.x = acc[mt][nt][0]; v.y = acc[mt][nt][1];
                *(float2*)(dst + (size_t)oc0*HW + px) = v;
            }
            if (oc1 < 27) {
                float2 v; v.x = acc[mt][nt][2]; v.y = acc[mt][nt][3];
                *(float2*)(dst + (size_t)oc1*HW + px) = v;
            }
        }
    }
}

// ---------------- kernel C v6: dcn HMMA + ldmatrix fragment loads ----------------
__global__ void __launch_bounds__(128, 4) dcn_kernel(
    const float* __restrict__ offm_b, const float* __restrict__ dcn_b,
    float* __restrict__ out)
{
    __shared__ __align__(16) __half S_h[128*64];
    __shared__ __align__(16) __half W_h[64*64];
    __shared__ int   sAi[4][128];
    __shared__ float sWm[4][128];

    int tid = threadIdx.x;
    int jb = blockIdx.y;
    int j = jb >> 1, b = jb & 1;
    int y = blockIdx.x;

    const __half* fbh = g_fnhwc_h + (size_t)(b*TT + j)*HW*64;
    const float* h0 = g_half + (size_t)((b*6 + 0)*27)*HW;
    const float* h1 = g_half + (size_t)((b*6 + 1 + j)*27)*HW;

    int lane = tid & 31;
    int warp = tid >> 5;
    int r4 = lane >> 2;
    int c2 = lane & 3;
    int w32 = warp * 32;

    // ldmatrix lane invariants
    int lrow  = lane & 7;
    int lhalf = (lane >> 3) & 1;
    int lkhi  = lane >> 4;
    uint32_t sbs = (uint32_t)__cvta_generic_to_shared(S_h);
    uint32_t wbs = (uint32_t)__cvta_generic_to_shared(W_h);
    uint32_t aRowAddr = wbs + (lhalf*8 + lrow)*128;         // + mt*16*128 + unit
    uint32_t bRowAddr = sbs + (w32 + (lane >> 3)*8 + lrow)*128;  // + unit

    float acc[4][4][4];
    #pragma unroll
    for (int mt = 0; mt < 4; mt++)
        #pragma unroll
        for (int nt = 0; nt < 4; nt++)
            #pragma unroll
            for (int f = 0; f < 4; f++) acc[mt][nt][f] = 0.f;

    char* Sb = (char*)S_h;

    for (int k = 0; k < 9; k++) {
        __syncthreads();

        {
            const float4* src4 = (const float4*)(g_wth + k*4096);
            float4* dst4 = (float4*)W_h;
            #pragma unroll
            for (int i = 0; i < 4; i++) dst4[tid + i*128] = src4[tid + i*128];
        }

        {
            int gx = tid;
            int pix = y*W + gx;
            float oy = h0[k*HW + pix] + h1[k*HW + pix] + offm_b[k];
            float ox = h0[(9+k)*HW + pix] + h1[(9+k)*HW + pix] + offm_b[9+k];
            float mm = h0[(18+k)*HW + pix] + h1[(18+k)*HW + pix] + offm_b[18+k];
            float mask = 1.f / (1.f + expf(-mm));
            float py  = (float)(y + (k/3) - 1) + oy;
            float pxf = (float)(gx + (k%3) - 1) + ox;
            float y0f = floorf(py), x0f = floorf(pxf);
            float lyf = py - y0f, lxf = pxf - x0f;
            int yi = (int)y0f, xi = (int)x0f;
            bool vy0 = (yi >= 0) & (yi < H);
            bool vy1 = (yi >= -1) & (yi < H-1);
            bool vx0 = (xi >= 0) & (xi < W);
            bool vx1 = (xi >= -1) & (xi < W-1);
            int yc0 = min(max(yi, 0), H-1);
            int yc1 = min(max(yi+1, 0), H-1);
            int xc0 = min(max(xi, 0), W-1);
            int xc1 = min(max(xi+1, 0), W-1);
            float wy0 = 1.f - lyf, wy1 = lyf, wx0 = 1.f - lxf, wx1 = lxf;
            sAi[0][tid] = (yc0*W + xc0) * 64;  sWm[0][tid] = (vy0 && vx0) ? wy0*wx0*mask : 0.f;
            sAi[1][tid] = (yc0*W + xc1) * 64;  sWm[1][tid] = (vy0 && vx1) ? wy0*wx1*mask : 0.f;
            sAi[2][tid] = (yc1*W + xc0) * 64;  sWm[2][tid] = (vy1 && vx0) ? wy1*wx0*mask : 0.f;
            sAi[3][tid] = (yc1*W + xc1) * 64;  sWm[3][tid] = (vy1 && vx1) ? wy1*wx1*mask : 0.f;
        }
        __syncthreads();

        #pragma unroll
        for (int it = 0; it < 8; it++) {
            int task = tid + it*128;
            int px = task >> 3;
            int qq = task & 7;
            int a0 = sAi[0][px], a1 = sAi[1][px];
            int a2 = sAi[2][px], a3 = sAi[3][px];
            ull w0 = pk2(sWm[0][px], sWm[0][px]);
            ull w1 = pk2(sWm[1][px], sWm[1][px]);
            ull w2 = pk2(sWm[2][px], sWm[2][px]);
            ull w3 = pk2(sWm[3][px], sWm[3][px]);
            uint4 v0 = *(const uint4*)(fbh + a0 + qq*8);
            uint4 v1 = *(const uint4*)(fbh + a1 + qq*8);
            uint4 v2 = *(const uint4*)(fbh + a2 + qq*8);
            uint4 v3 = *(const uint4*)(fbh + a3 + qq*8);
            const uint32_t* p0 = (const uint32_t*)&v0;
            const uint32_t* p1 = (const uint32_t*)&v1;
            const uint32_t* p2 = (const uint32_t*)&v2;
            const uint32_t* p3 = (const uint32_t*)&v3;
            uint4 outv;
            uint32_t* po = (uint32_t*)&outv;
            #pragma unroll
            for (int i = 0; i < 4; i++) {
                float2 f0 = __half22float2(*(const __half2*)&p0[i]);
                float2 f1 = __half22float2(*(const __half2*)&p1[i]);
                float2 f2 = __half22float2(*(const __half2*)&p2[i]);
                float2 f3 = __half22float2(*(const __half2*)&p3[i]);
                ull r = 0ULL;
                ffma2(r, w0, pk2(f0.x, f0.y));
                ffma2(r, w1, pk2(f1.x, f1.y));
                ffma2(r, w2, pk2(f2.x, f2.y));
                ffma2(r, w3, pk2(f3.x, f3.y));
                float2 rf = upk2(r);
                __half2 h = __float22half2_rn(rf);
                po[i] = *(uint32_t*)&h;
            }
            int byteoff = px*128 + ((qq ^ (px & 7)) << 4);
            *(uint4*)(Sb + byteoff) = outv;
        }
        __syncthreads();

        // HMMA GEMM via ldmatrix: per ks, 4 A-ldsm (mt) + 2 B-ldsm
        #pragma unroll
        for (int ks = 0; ks < 4; ks++) {
            uint32_t afr[4][4];
            uint32_t aUnit = (uint32_t)((ks*2 + lkhi) ^ lrow) << 4;
            #pragma unroll
            for (int mt = 0; mt < 4; mt++) {
                ldsm_x4(afr[mt][0], afr[mt][1], afr[mt][2], afr[mt][3],
                        aRowAddr + mt*16*128 + aUnit);
            }
            uint32_t blo[4], bhi[4];
            ldsm_x4(blo[0], blo[1], blo[2], blo[3],
                    bRowAddr + ((uint32_t)((ks*2) ^ lrow) << 4));
            ldsm_x4(bhi[0], bhi[1], bhi[2], bhi[3],
                    bRowAddr + ((uint32_t)((ks*2 + 1) ^ lrow) << 4));
            #pragma unroll
            for (int mt = 0; mt < 4; mt++)
                #pragma unroll
                for (int nt = 0; nt < 4; nt++) {
                    uint32_t bb[2] = { blo[nt], bhi[nt] };
                    mma16816(acc[mt][nt], afr[mt], bb);
                }
        }
    }

    #pragma unroll
    for (int mt = 0; mt < 4; mt++) {
        int oc = mt*16 + r4;
        float bi0 = __ldg(&dcn_b[oc]);
        float bi8 = __ldg(&dcn_b[oc + 8]);
        #pragma unroll
        for (int nt = 0; nt < 4; nt++) {
            int px = w32 + nt*8 + c2*2;
            float* o0 = out + ((size_t)jb*64 + oc)*HW + y*W + px;
            float* o8 = out + ((size_t)jb*64 + oc + 8)*HW + y*W + px;
            float2 v0, v1;
            v0.x = acc[mt][nt][0] + bi0; v0.y = acc[mt][nt][1] + bi0;
            v1.x = acc[mt][nt][2] + bi8; v1.y = acc[mt][nt][3] + bi8;
            *(float2*)o0 = v0;
            *(float2*)o8 = v1;
        }
    }
}

// ---------------- launch ----------------
extern "C" void kernel_launch(void* const* d_in, const int* in_sizes, int n_in,
                              void* d_out, int out_size) {
    const float* x       = (const float*)d_in[0];
    const float* init_w  = (const float*)d_in[1];
    const float* init_b  = (const float*)d_in[2];
    const float* prelu_a = (const float*)d_in[3];
    const float* offm_w  = (const float*)d_in[4];
    const float* offm_b  = (const float*)d_in[5];
    const float* dcn_w   = (const float*)d_in[6];
    const float* dcn_b   = (const float*)d_in[7];
    float* out = (float*)d_out;

    static bool attr_set = false;
    if (!attr_set) {
        cudaFuncSetAttribute(half_conv_kernel, cudaFuncAttributeMaxDynamicSharedMemorySize, 58880);
        attr_set = true;
    }

    wth_prep_kernel<<<(9*64*64 + 255)/256, 256>>>(dcn_w);
    hwh_prep_kernel<<<(2*9*32*64 + 255)/256, 256>>>(offm_w);
    init_conv_kernel<<<dim3(64, 10), 256>>>(x, init_w, init_b, prelu_a);
    half_conv_kernel<<<dim3(128, 12), 128, 58880>>>();
    dcn_kernel<<<dim3(128, 10), 128>>>(offm_b, dcn_b, out);
}